// round 15
// baseline (speedup 1.0000x reference)
#include <cuda_runtime.h>
#include <cuda_bf16.h>
#include <math.h>
#include <stdint.h>

#define EPSF 1e-5f

// ---------------- scratch (device globals) ----------------
__device__ float g_qkv[4194304];      // [128 bh][256 o][128 l]
__device__ float g_outraw[4194304];   // [128 bh][256 o][128 i]
__device__ float g_qkvStats[512];     // [256 ch][sum,sumsq]
__device__ float g_simStats[96];
__device__ float g_outStats[512];
__device__ float g_outScale[256];
__device__ float g_outShift[256];

__device__ __forceinline__ float warpSum(float v) {
#pragma unroll
    for (int o = 16; o > 0; o >>= 1) v += __shfl_xor_sync(0xffffffffu, v, o);
    return v;
}

// sum across the 8 lanes differing in bits 0..2 (tx groups in kA)
__device__ __forceinline__ float txSum(float v) {
    v += __shfl_xor_sync(0xffffffffu, v, 1);
    v += __shfl_xor_sync(0xffffffffu, v, 2);
    v += __shfl_xor_sync(0xffffffffu, v, 4);
    return v;
}

// reduce across lanes that differ only in bits 2..4 (rw groups, cl fixed)
__device__ __forceinline__ float rwSum(float v) {
    v += __shfl_xor_sync(0xffffffffu, v, 4);
    v += __shfl_xor_sync(0xffffffffu, v, 8);
    v += __shfl_xor_sync(0xffffffffu, v, 16);
    return v;
}

__device__ __forceinline__ uint32_t tf32r(float x) {
    uint32_t u;
    asm("cvt.rna.tf32.f32 %0, %1;" : "=r"(u) : "f"(x));
    return u;
}

__device__ __forceinline__ uint32_t packbf(float a, float b) {
    __nv_bfloat162 h = __floats2bfloat162_rn(a, b);
    return *(uint32_t*)&h;
}

// 2^t on the FMA/ALU pipes (no MUFU). t <= 0 (post max-subtraction).
// Magic-constant round-to-nearest + deg-4 Taylor exp2 on [-0.5,0.5] (~5e-5 rel).
__device__ __forceinline__ float fexp2t(float t) {
    t = fmaxf(t, -126.f);
    float m = t + 12582912.f;                       // RNE integer round via magic
    int ri = __float_as_int(m) - 0x4B400000;        // (int)round(t)
    float r = m - 12582912.f;
    float f = t - r;                                // f in [-0.5, 0.5]
    float p = fmaf(9.618129e-3f, f, 5.550411e-2f);
    p = fmaf(p, f, 2.402265e-1f);
    p = fmaf(p, f, 6.931472e-1f);
    p = fmaf(p, f, 1.0f);
    return __int_as_float(__float_as_int(p) + (ri << 23));
}

__device__ __forceinline__ void mma8(float* c, const uint32_t* a, uint32_t b0, uint32_t b1) {
    asm volatile(
        "mma.sync.aligned.m16n8k8.row.col.f32.tf32.tf32.f32 "
        "{%0,%1,%2,%3},{%4,%5,%6,%7},{%8,%9},{%0,%1,%2,%3};\n"
        : "+f"(c[0]), "+f"(c[1]), "+f"(c[2]), "+f"(c[3])
        : "r"(a[0]), "r"(a[1]), "r"(a[2]), "r"(a[3]), "r"(b0), "r"(b1));
}

__device__ __forceinline__ void mma16(float* c, const uint32_t* a, uint32_t b0, uint32_t b1) {
    asm volatile(
        "mma.sync.aligned.m16n8k16.row.col.f32.bf16.bf16.f32 "
        "{%0,%1,%2,%3},{%4,%5,%6,%7},{%8,%9},{%0,%1,%2,%3};\n"
        : "+f"(c[0]), "+f"(c[1]), "+f"(c[2]), "+f"(c[3])
        : "r"(a[0]), "r"(a[1]), "r"(a[2]), "r"(a[3]), "r"(b0), "r"(b1));
}

// ---------------- Z: zero stat accumulators ----------------
__global__ void kZero() {
    int t = threadIdx.x;  // 512
    if (t < 96) g_simStats[t] = 0.f;
    g_outStats[t & 511] = 0.f;
    g_qkvStats[t & 511] = 0.f;
}

// ---------------- A: qkv GEMM, 8x8 thread tiles + fused BN stats ----------------
// grid (4, 128): bx = ot*2 + jh. 128 thr, smem ~100KB -> 2 CTAs/SM.
__global__ __launch_bounds__(128) void kA(const float* __restrict__ x,
                                          const float* __restrict__ W) {
    extern __shared__ float sm[];
    float* sa = sm;              // [128 k][132]  W^T tile (k-major)
    float* sb = sm + 16896;      // [128 k][68]   x tile (j-half)
    const int ot = blockIdx.x >> 1, jh = blockIdx.x & 1, bh = blockIdx.y;
    const int b0 = bh >> 6, h = bh & 63;
    const int t = threadIdx.x;

    for (int e = 0; e < 128; e++) {
        int idx = e * 128 + t;
        int r = idx >> 7, c = idx & 127;
        sa[c * 132 + r] = W[(ot * 128 + r) * 128 + c];
    }
    for (int e = 0; e < 64; e++) {
        int idx = e * 128 + t;
        int c = idx >> 6, l0 = idx & 63;
        sb[c * 68 + l0] = x[((b0 * 128 + c) * 64 + h) * 128 + jh * 64 + l0];
    }
    __syncthreads();

    const int ty = t >> 3, tx = t & 7;
    const int i0 = ty * 8, j0 = tx * 8;
    float acc[8][8];
#pragma unroll
    for (int u = 0; u < 8; u++)
#pragma unroll
        for (int v = 0; v < 8; v++) acc[u][v] = 0.f;

#pragma unroll 2
    for (int k = 0; k < 128; k++) {
        float4 A0 = *(const float4*)(sa + k * 132 + i0);
        float4 A1 = *(const float4*)(sa + k * 132 + i0 + 4);
        float4 B0 = *(const float4*)(sb + k * 68 + j0);
        float4 B1 = *(const float4*)(sb + k * 68 + j0 + 4);
        float a[8] = {A0.x, A0.y, A0.z, A0.w, A1.x, A1.y, A1.z, A1.w};
        float b[8] = {B0.x, B0.y, B0.z, B0.w, B1.x, B1.y, B1.z, B1.w};
#pragma unroll
        for (int u = 0; u < 8; u++)
#pragma unroll
            for (int v = 0; v < 8; v++) acc[u][v] += a[u] * b[v];
    }

    float* dst = g_qkv + (size_t)bh * 32768 + (size_t)(ot * 128) * 128 + jh * 64;
#pragma unroll
    for (int u = 0; u < 8; u++) {
        *(float4*)(dst + (i0 + u) * 128 + j0)     = make_float4(acc[u][0], acc[u][1], acc[u][2], acc[u][3]);
        *(float4*)(dst + (i0 + u) * 128 + j0 + 4) = make_float4(acc[u][4], acc[u][5], acc[u][6], acc[u][7]);
        float s = 0.f, s2 = 0.f;
#pragma unroll
        for (int v = 0; v < 8; v++) { s += acc[u][v]; s2 += acc[u][v] * acc[u][v]; }
        s = txSum(s);
        s2 = txSum(s2);
        if (tx == 0) {
            int ch = ot * 128 + i0 + u;
            atomicAdd(&g_qkvStats[ch * 2], s);
            atomicAdd(&g_qkvStats[ch * 2 + 1], s2);
        }
    }
}

// ---------------- C: fused qkv-BN + bf16 build + bf16 m16n8k16 qk + sim stats -------
// smem 80KB -> 2 CTAs/SM. grid (16, 128), 512 thr
__global__ __launch_bounds__(512, 2) void kC(const float* __restrict__ relemb,
                                             const float* __restrict__ gamma,
                                             const float* __restrict__ beta) {
    extern __shared__ float sm[];
    float* sreq = sm;            // [255][4]
    float* srek = sm + 1024;
    float* sq4  = sm + 2048;     // [128][4]
    float* sk4  = sm + 2560;
    uint32_t* sqe16 = (uint32_t*)(sm + 3072);    // [128 i][68 words], word = (m0,m1) bf16x2
    uint32_t* ske16 = (uint32_t*)(sm + 11776);   // [128 j][68 words]
    __shared__ float qscl[8], qsft[8];
    const int g = blockIdx.x, bh = blockIdx.y, t = threadIdx.x;
    const int lane = t & 31, w = t >> 5;

    if (t < 8) {
        int o = g * 16 + t;
        float S = g_qkvStats[o * 2], S2 = g_qkvStats[o * 2 + 1];
        float mean = S * (1.f / 16384.f);
        float var  = S2 * (1.f / 16384.f) - mean * mean;
        float sc = gamma[o] * rsqrtf(var + EPSF);
        qscl[t] = sc;
        qsft[t] = beta[o] - mean * sc;
    }
    __syncthreads();

    for (int n = t; n < 1020; n += 512) {
        int c = n & 3, d = n >> 2;
        sreq[n] = relemb[c * 255 + d];
        srek[n] = relemb[(4 + c) * 255 + d];
    }
    for (int n = t; n < 1024; n += 512) {
        int c8 = n >> 7, m = n & 127;
        int o = g * 16 + c8;
        float v = g_qkv[(size_t)bh * 32768 + o * 128 + m] * qscl[c8] + qsft[c8];
        if (c8 < 4) sq4[m * 4 + c8] = v; else sk4[m * 4 + c8 - 4] = v;
    }
    __syncthreads();

    // build: thread handles (m-pair mh, i)
    float sQE = 0.f, sQE2 = 0.f, sKE = 0.f, sKE2 = 0.f;
    for (int e = 0; e < 16; e++) {
        int idx = e * 512 + t;
        int mh = idx >> 7;        // 0..63
        int i  = idx & 127;
        int m0 = mh * 2;
        float4 qa = *(const float4*)(sq4 + 4 * m0);
        float4 qb = *(const float4*)(sq4 + 4 * m0 + 4);
        float4 ka = *(const float4*)(sk4 + 4 * m0);
        float4 kb = *(const float4*)(sk4 + 4 * m0 + 4);
        int d0 = m0 - i + 127;
        float4 rq0 = *(const float4*)(sreq + 4 * d0);
        float4 rq1 = *(const float4*)(sreq + 4 * d0 + 4);
        float4 rk0 = *(const float4*)(srek + 4 * d0);
        float4 rk1 = *(const float4*)(srek + 4 * d0 + 4);
        float qe0 = qa.x * rq0.x + qa.y * rq0.y + qa.z * rq0.z + qa.w * rq0.w;
        float qe1 = qb.x * rq1.x + qb.y * rq1.y + qb.z * rq1.z + qb.w * rq1.w;
        float ke0 = ka.x * rk0.x + ka.y * rk0.y + ka.z * rk0.z + ka.w * rk0.w;
        float ke1 = kb.x * rk1.x + kb.y * rk1.y + kb.z * rk1.z + kb.w * rk1.w;
        sQE += qe0 + qe1; sQE2 += qe0 * qe0 + qe1 * qe1;
        sKE += ke0 + ke1; sKE2 += ke0 * ke0 + ke1 * ke1;
        sqe16[i * 68 + mh] = packbf(qe0, qe1);
        ske16[i * 68 + mh] = packbf(ke0, ke1);
    }
    __syncthreads();

    // qk = qe^T * ke via bf16 m16n8k16. 16 warps, tile 32(i) x 32(j).
    const int i0w = (w >> 2) * 32, j0w = (w & 3) * 32;
    const int rw = lane >> 2, cl = lane & 3;
    float c[2][4][4];
#pragma unroll
    for (int ii = 0; ii < 2; ii++)
#pragma unroll
        for (int jj = 0; jj < 4; jj++)
#pragma unroll
            for (int u = 0; u < 4; u++) c[ii][jj][u] = 0.f;

    for (int kc = 0; kc < 8; kc++) {
        const int kw = kc * 8;
        uint32_t a[2][4];
#pragma unroll
        for (int ii = 0; ii < 2; ii++) {
            const uint32_t* base = sqe16 + (i0w + ii * 16 + rw) * 68 + kw + cl;
            a[ii][0] = base[0];
            a[ii][1] = base[8 * 68];
            a[ii][2] = base[4];
            a[ii][3] = base[8 * 68 + 4];
        }
#pragma unroll
        for (int jj = 0; jj < 4; jj++) {
            const uint32_t* bb = ske16 + (j0w + jj * 8 + rw) * 68 + kw + cl;
            uint32_t b0 = bb[0];
            uint32_t b1 = bb[4];
            mma16(c[0][jj], a[0], b0, b1);
            mma16(c[1][jj], a[1], b0, b1);
        }
    }

    float sQK = 0.f, sQK2 = 0.f;
#pragma unroll
    for (int ii = 0; ii < 2; ii++)
#pragma unroll
        for (int jj = 0; jj < 4; jj++)
#pragma unroll
            for (int u = 0; u < 4; u++) { float q = c[ii][jj][u]; sQK += q; sQK2 += q * q; }

    sQK = warpSum(sQK); sQK2 = warpSum(sQK2);
    sQE = warpSum(sQE); sQE2 = warpSum(sQE2);
    sKE = warpSum(sKE); sKE2 = warpSum(sKE2);
    float* red = sq4;  // reuse
    if (lane == 0) {
        red[w * 8 + 0] = sQK; red[w * 8 + 1] = sQK2;
        red[w * 8 + 2] = sQE; red[w * 8 + 3] = sQE2;
        red[w * 8 + 4] = sKE; red[w * 8 + 5] = sKE2;
    }
    __syncthreads();
    if (t < 6) {
        float tot = 0.f;
        for (int i = 0; i < 16; i++) tot += red[i * 8 + t];
        int ch = (t < 2) ? g : (t < 4) ? (16 + g) : (32 + g);
        atomicAdd(&g_simStats[ch * 2 + (t & 1)], tot);
    }
}

// ---------------- E: fused BN + qk MMA + FMA-pipe softmax + am/ame ----------------
// grid (16, 128), 512 thr
__global__ __launch_bounds__(512) void kE(const float* __restrict__ relemb,
                                          const float* __restrict__ gamma,
                                          const float* __restrict__ beta,
                                          const float* __restrict__ gamma_sim) {
    extern __shared__ float sm[];
    float* sreq = sm;            // [255][4]
    float* srek = sm + 1024;
    float* srva = sm + 2048;     // v rel ch 0..3 [d][4]
    float* srvb = sm + 3072;     // v rel ch 4..7 [d][4]
    float* sq4  = sm + 4096;     // [128][4]
    float* sk4  = sm + 4608;
    float* sv8  = sm + 5120;     // v all 8 ch [j][8] (tf32-rounded)
    float* schkA = sm + 6144;    // [128][4] row-chunk max
    float* schkB = sm + 6656;    // [128][4] row-chunk sum
    float* sqe  = sm + 7168;     // [128][136] tf32-rounded; aliased by ssim later
    float* ske  = sm + 24576;    // [128][136]; aliased by amePart later
    float* ssim = sqe;           // [128][133] final p (tf32-rounded)
    float* amePart = ske;        // [8 c][4 strip][128 i]
    __shared__ float qscl[16], qsft[16], sscale[3];
    const int g = blockIdx.x, bh = blockIdx.y, t = threadIdx.x;
    const int lane = t & 31, w = t >> 5;
    const int rw = lane >> 2, cl = lane & 3;

    if (t < 16) {
        int o = g * 16 + t;
        float S = g_qkvStats[o * 2], S2 = g_qkvStats[o * 2 + 1];
        float mean = S * (1.f / 16384.f);
        float var  = S2 * (1.f / 16384.f) - mean * mean;
        float sc = gamma[o] * rsqrtf(var + EPSF);
        qscl[t] = sc;
        qsft[t] = beta[o] - mean * sc;
    } else if (t < 19) {
        int idx = t - 16;                 // 0..2
        int ch = idx * 16 + g;
        const float N = 2097152.f;
        float S = g_simStats[ch * 2], S2 = g_simStats[ch * 2 + 1];
        float mean = S / N;
        float var = S2 / N - mean * mean;
        // fold log2(e): softmax computed base-2 (2^(log2e*x) == e^x)
        sscale[idx] = gamma_sim[ch] * rsqrtf(var + EPSF) * 1.4426950408889634f;
    }
    __syncthreads();

    for (int n = t; n < 1020; n += 512) {
        int c = n & 3, d = n >> 2;
        sreq[n] = relemb[c * 255 + d];
        srek[n] = relemb[(4 + c) * 255 + d];
        srva[n] = relemb[(8 + c) * 255 + d];
        srvb[n] = relemb[(12 + c) * 255 + d];
    }
    for (int n = t; n < 2048; n += 512) {
        int c8 = n >> 7, m = n & 127;
        int o = g * 16 + c8;
        float v = g_qkv[(size_t)bh * 32768 + o * 128 + m] * qscl[c8] + qsft[c8];
        if (c8 < 4)       sq4[m * 4 + c8] = v;
        else if (c8 < 8)  sk4[m * 4 + c8 - 4] = v;
        else              sv8[m * 8 + c8 - 8] = __uint_as_float(tf32r(v));
    }
    __syncthreads();

    for (int e = 0; e < 32; e++) {
        int idx = e * 512 + t;
        int m = idx >> 7, i = idx & 127;
        int d = m - i + 127;
        float4 qv = *(const float4*)(sq4 + 4 * m);
        float4 rq = *(const float4*)(sreq + 4 * d);
        float4 kv = *(const float4*)(sk4 + 4 * m);
        float4 rk = *(const float4*)(srek + 4 * d);
        float qe = qv.x * rq.x + qv.y * rq.y + qv.z * rq.z + qv.w * rq.w;
        float ke = kv.x * rk.x + kv.y * rk.y + kv.z * rk.z + kv.w * rk.w;
        sqe[m * 136 + i] = __uint_as_float(tf32r(qe));
        ske[m * 136 + i] = __uint_as_float(tf32r(ke));
    }
    __syncthreads();

    // qk MMA: 16 warps, 32x32 tiles, + combine into fragments
    const float a1 = sscale[0], a2 = sscale[1], a3 = sscale[2];
    const int i0w = (w >> 2) * 32, j0w = (w & 3) * 32;
    float c[2][4][4];
#pragma unroll
    for (int ii = 0; ii < 2; ii++)
#pragma unroll
        for (int jj = 0; jj < 4; jj++)
#pragma unroll
            for (int u = 0; u < 4; u++) c[ii][jj][u] = 0.f;

    for (int kc = 0; kc < 16; kc++) {
        const int k0 = kc * 8;
        uint32_t a[2][4];
#pragma unroll
        for (int ii = 0; ii < 2; ii++) {
            const float* base = sqe + (k0 + cl) * 136 + i0w + ii * 16 + rw;
            a[ii][0] = __float_as_uint(base[0]);
            a[ii][1] = __float_as_uint(base[8]);
            a[ii][2] = __float_as_uint(base[4 * 136]);
            a[ii][3] = __float_as_uint(base[4 * 136 + 8]);
        }
#pragma unroll
        for (int jj = 0; jj < 4; jj++) {
            const float* bb = ske + (k0 + cl) * 136 + j0w + jj * 8 + rw;
            uint32_t b0 = __float_as_uint(bb[0]);
            uint32_t b1 = __float_as_uint(bb[4 * 136]);
            mma8(c[0][jj], a[0], b0, b1);
            mma8(c[1][jj], a[1], b0, b1);
        }
    }

    // combine: sim' = log2e*(a1*qk + a2*qe + a3*ke) at fragment coords (log2e folded)
#pragma unroll
    for (int ii = 0; ii < 2; ii++)
#pragma unroll
        for (int jj = 0; jj < 4; jj++) {
            int ir0 = i0w + ii * 16 + rw;
            int jc = j0w + jj * 8 + 2 * cl;
            float2 q0 = *(const float2*)(sqe + ir0 * 136 + jc);
            float2 k0 = *(const float2*)(ske + ir0 * 136 + jc);
            float2 q1 = *(const float2*)(sqe + (ir0 + 8) * 136 + jc);
            float2 k1 = *(const float2*)(ske + (ir0 + 8) * 136 + jc);
            float* cc = c[ii][jj];
            cc[0] = a1 * cc[0] + a2 * q0.x + a3 * k0.x;
            cc[1] = a1 * cc[1] + a2 * q0.y + a3 * k0.y;
            cc[2] = a1 * cc[2] + a2 * q1.x + a3 * k1.x;
            cc[3] = a1 * cc[3] + a2 * q1.y + a3 * k1.y;
        }

    // ---- in-register softmax over j (base-2; exp on FMA pipe, no MUFU) ----
    float mx[4];
#pragma unroll
    for (int r = 0; r < 4; r++) mx[r] = -1e30f;
#pragma unroll
    for (int jj = 0; jj < 4; jj++) {
        mx[0] = fmaxf(mx[0], fmaxf(c[0][jj][0], c[0][jj][1]));
        mx[1] = fmaxf(mx[1], fmaxf(c[0][jj][2], c[0][jj][3]));
        mx[2] = fmaxf(mx[2], fmaxf(c[1][jj][0], c[1][jj][1]));
        mx[3] = fmaxf(mx[3], fmaxf(c[1][jj][2], c[1][jj][3]));
    }
#pragma unroll
    for (int o = 1; o <= 2; o <<= 1)
#pragma unroll
        for (int r = 0; r < 4; r++)
            mx[r] = fmaxf(mx[r], __shfl_xor_sync(0xffffffffu, mx[r], o));
    if (cl == 0) {
        int jt = w & 3;
        schkA[(i0w + rw) * 4 + jt]      = mx[0];
        schkA[(i0w + rw + 8) * 4 + jt]  = mx[1];
        schkA[(i0w + rw + 16) * 4 + jt] = mx[2];
        schkA[(i0w + rw + 24) * 4 + jt] = mx[3];
    }
    __syncthreads();
    float gmx[4];
#pragma unroll
    for (int r = 0; r < 4; r++) {
        float4 m4 = *(const float4*)(schkA + (i0w + rw + r * 8) * 4);
        gmx[r] = fmaxf(fmaxf(m4.x, m4.y), fmaxf(m4.z, m4.w));
    }
    float sums[4] = {0.f, 0.f, 0.f, 0.f};
#pragma unroll
    for (int jj = 0; jj < 4; jj++) {
        c[0][jj][0] = fexp2t(c[0][jj][0] - gmx[0]);
        c[0][jj][1] = fexp2t(c[0][jj][1] - gmx[0]);
        sums[0] += c[0][jj][0] + c[0][jj][1];
        c[0][jj][2] = fexp2t(c[0][jj][2] - gmx[1]);
        c[0][jj][3] = fexp2t(c[0][jj][3] - gmx[1]);
        sums[1] += c[0][jj][2] + c[0][jj][3];
        c[1][jj][0] = fexp2t(c[1][jj][0] - gmx[2]);
        c[1][jj][1] = fexp2t(c[1][jj][1] - gmx[2]);
        sums[2] += c[1][jj][0] + c[1][jj][1];
        c[1][jj][2] = fexp2t(c[1][jj][2] - gmx[3]);
        c[1][jj][3] = fexp2t(c[1][jj][3] - gmx[3]);
        sums[3] += c[1][jj][2] + c[1][jj][3];
    }
#pragma unroll
    for (int o = 1; o <= 2; o <<= 1)
#pragma unroll
        for (int r = 0; r < 4; r++)
            sums[r] += __shfl_xor_sync(0xffffffffu, sums[r], o);
    if (cl == 0) {
        int jt = w & 3;
        schkB[(i0w + rw) * 4 + jt]      = sums[0];
        schkB[(i0w + rw + 8) * 4 + jt]  = sums[1];
        schkB[(i0w + rw + 16) * 4 + jt] = sums[2];
        schkB[(i0w + rw + 24) * 4 + jt] = sums[3];
    }
    __syncthreads();
    float inv[4];
#pragma unroll
    for (int r = 0; r < 4; r++) {
        float4 s4 = *(const float4*)(schkB + (i0w + rw + r * 8) * 4);
        inv[r] = 1.f / (s4.x + s4.y + s4.z + s4.w);
    }
    // write final p (tf32-rounded) to ssim — SCALAR stores (pitch 133 odd)
#pragma unroll
    for (int ii = 0; ii < 2; ii++)
#pragma unroll
        for (int jj = 0; jj < 4; jj++) {
            int ir0 = i0w + ii * 16 + rw;
            int jc = j0w + jj * 8 + 2 * cl;
            float* cc = c[ii][jj];
            float ivl = inv[ii * 2], ivh = inv[ii * 2 + 1];
            ssim[ir0 * 133 + jc]           = __uint_as_float(tf32r(cc[0] * ivl));
            ssim[ir0 * 133 + jc + 1]       = __uint_as_float(tf32r(cc[1] * ivl));
            ssim[(ir0 + 8) * 133 + jc]     = __uint_as_float(tf32r(cc[2] * ivh));
            ssim[(ir0 + 8) * 133 + jc + 1] = __uint_as_float(tf32r(cc[3] * ivh));
        }
    __syncthreads();

    // ame strips: thread owns (i, strip of 32 j), all 8 channels -> partials to smem
    {
        const int i = t & 127, s = t >> 7;
        float accE[8] = {0.f, 0.f, 0.f, 0.f, 0.f, 0.f, 0.f, 0.f};
        const int jb = s * 32;
        for (int jj = 0; jj < 32; jj++) {
            int j = jb + jj;
            float p = ssim[i * 133 + j];
            int d = i - j + 127;
            float4 ra = *(const float4*)(srva + 4 * d);
            float4 rb = *(const float4*)(srvb + 4 * d);
            accE[0] += p * ra.x; accE[1] += p * ra.y; accE[2] += p * ra.z; accE[3] += p * ra.w;
            accE[4] += p * rb.x; accE[5] += p * rb.y; accE[6] += p * rb.z; accE[7] += p * rb.w;
        }
        __syncthreads();   // ske reads fully done earlier; amePart aliases ske
#pragma unroll
        for (int ch = 0; ch < 8; ch++)
            amePart[ch * 512 + s * 128 + i] = accE[ch];
    }
    __syncthreads();

    float* dst = g_outraw + (size_t)bh * 32768;
    if (w < 8) {
        // am via tf32 MMA: A = P (ssim, pre-rounded), B = v (sv8, pre-rounded)
        const int i0 = w * 16;
        float ca[4] = {0.f, 0.f, 0.f, 0.f};
        for (int kc = 0; kc < 16; kc++) {
            const int k0 = kc * 8;
            const float* pr0 = ssim + (i0 + rw) * 133 + k0 + cl;
            const float* pr1 = pr0 + 8 * 133;
            uint32_t a[4];
            a[0] = __float_as_uint(pr0[0]);
            a[1] = __float_as_uint(pr1[0]);
            a[2] = __float_as_uint(pr0[4]);
            a[3] = __float_as_uint(pr1[4]);
            uint32_t b0 = __float_as_uint(sv8[(k0 + cl) * 8 + rw]);
            uint32_t b1 = __float_as_uint(sv8[(k0 + cl + 4) * 8 + rw]);
            mma8(ca, a, b0, b1);
        }
        const int i1 = i0 + rw, i2 = i0 + rw + 8;
        const int ch0 = 2 * cl, ch1 = 2 * cl + 1;
        const int o0 = g * 16 + 2 * ch0, o1 = g * 16 + 2 * ch1;
        dst[o0 * 128 + i1] = ca[0];
        dst[o1 * 128 + i1] = ca[1];
        dst[o0 * 128 + i2] = ca[2];
        dst[o1 * 128 + i2] = ca[3];
        float s0 = ca[0] + ca[2], s02 = ca[0] * ca[0] + ca[2] * ca[2];
        float s1 = ca[1] + ca[3], s12 = ca[1] * ca[1] + ca[3] * ca[3];
        s0 = rwSum(s0); s02 = rwSum(s02); s1 = rwSum(s1); s12 = rwSum(s12);
        if (rw == 0) {
            atomicAdd(&g_outStats[o0 * 2], s0);
            atomicAdd(&g_outStats[o0 * 2 + 1], s02);
            atomicAdd(&g_outStats[o1 * 2], s1);
            atomicAdd(&g_outStats[o1 * 2 + 1], s12);
        }
    } else {
        // ame reduce: warp handles one channel; lane covers 4 consecutive i
        const int ch = w - 8;
        const int iB = lane * 4;
        float4 v0 = *(const float4*)(amePart + ch * 512 + 0 * 128 + iB);
        float4 v1 = *(const float4*)(amePart + ch * 512 + 1 * 128 + iB);
        float4 v2 = *(const float4*)(amePart + ch * 512 + 2 * 128 + iB);
        float4 v3 = *(const float4*)(amePart + ch * 512 + 3 * 128 + iB);
        float4 r4 = make_float4(v0.x + v1.x + v2.x + v3.x,
                                v0.y + v1.y + v2.y + v3.y,
                                v0.z + v1.z + v2.z + v3.z,
                                v0.w + v1.w + v2.w + v3.w);
        const int o = g * 16 + 2 * ch + 1;
        *(float4*)(dst + o * 128 + iB) = r4;
        float sE = r4.x + r4.y + r4.z + r4.w;
        float sE2 = r4.x * r4.x + r4.y * r4.y + r4.z * r4.z + r4.w * r4.w;
        sE = warpSum(sE); sE2 = warpSum(sE2);
        if (lane == 0) {
            atomicAdd(&g_outStats[o * 2], sE);
            atomicAdd(&g_outStats[o * 2 + 1], sE2);
        }
    }
}

// ---------------- F: finalize out BN params ----------------
__global__ void kF(const float* __restrict__ gamma_out, const float* __restrict__ beta_out) {
    int o = threadIdx.x;  // 256
    const float N = 16384.f;
    float S = g_outStats[o * 2], S2 = g_outStats[o * 2 + 1];
    float mean = S / N;
    float var = S2 / N - mean * mean;
    float sc = gamma_out[o] * rsqrtf(var + EPSF);
    g_outScale[o] = sc;
    g_outShift[o] = beta_out[o] - mean * sc;
}

// ---------------- G: y = bn(out)[2oc] + bn(out)[2oc+1] ----------------
__global__ __launch_bounds__(256) void kG(float* __restrict__ y) {
    int idx = blockIdx.x * 256 + threadIdx.x;
    int wpos = idx & 127;
    int h = (idx >> 7) & 63;
    int oc = (idx >> 13) & 127;
    int b0 = idx >> 20;
    int bh = b0 * 64 + h;
    int o = oc * 2;
    float v0 = g_outraw[(size_t)bh * 32768 + o * 128 + wpos];
    float v1 = g_outraw[(size_t)bh * 32768 + (o + 1) * 128 + wpos];
    y[idx] = (v0 * g_outScale[o] + g_outShift[o]) + (v1 * g_outScale[o + 1] + g_outShift[o + 1]);
}

// ---------------- launch ----------------
extern "C" void kernel_launch(void* const* d_in, const int* in_sizes, int n_in,
                              void* d_out, int out_size) {
    const float* x  = (const float*)d_in[0];
    const float* W  = (const float*)d_in[1];
    const float* gq = (const float*)d_in[2];
    const float* bq = (const float*)d_in[3];
    const float* re = (const float*)d_in[4];
    const float* gs = (const float*)d_in[5];
    // beta_sim (d_in[6]) cancels inside softmax — unused
    const float* go = (const float*)d_in[7];
    const float* bo = (const float*)d_in[8];
    float* y = (float*)d_out;

    const int SMEM_A = (16896 + 128 * 68) * 4;       // 102400
    const int SMEM_C = 20480 * 4;                    // 81920 -> 2 CTAs/SM
    const int SMEM_E = (24576 + 17408) * 4;          // 167936

    cudaFuncSetAttribute(kA, cudaFuncAttributeMaxDynamicSharedMemorySize, SMEM_A);
    cudaFuncSetAttribute(kC, cudaFuncAttributeMaxDynamicSharedMemorySize, SMEM_C);
    cudaFuncSetAttribute(kE, cudaFuncAttributeMaxDynamicSharedMemorySize, SMEM_E);

    kZero<<<1, 512>>>();
    kA<<<dim3(4, 128), 128, SMEM_A>>>(x, W);
    kC<<<dim3(16, 128), 512, SMEM_C>>>(re, gq, bq);
    kE<<<dim3(16, 128), 512, SMEM_E>>>(re, gq, bq, gs);
    kF<<<1, 256>>>(go, bo);
    kG<<<8192, 256>>>(y);
}

// round 16
// speedup vs baseline: 1.1082x; 1.1082x over previous
#include <cuda_runtime.h>
#include <cuda_bf16.h>
#include <cuda_fp16.h>
#include <math.h>
#include <stdint.h>

#define EPSF 1e-5f

// ---------------- scratch (device globals) ----------------
__device__ float g_qkv[4194304];      // [128 bh][256 o][128 l]
__device__ float g_outraw[4194304];   // [128 bh][256 o][128 i]
__device__ float g_qkvStats[512];     // [256 ch][sum,sumsq]
__device__ float g_simStats[96];
__device__ float g_outStats[512];
__device__ float g_outScale[256];
__device__ float g_outShift[256];

__device__ __forceinline__ float warpSum(float v) {
#pragma unroll
    for (int o = 16; o > 0; o >>= 1) v += __shfl_xor_sync(0xffffffffu, v, o);
    return v;
}

__device__ __forceinline__ float txSum(float v) {
    v += __shfl_xor_sync(0xffffffffu, v, 1);
    v += __shfl_xor_sync(0xffffffffu, v, 2);
    v += __shfl_xor_sync(0xffffffffu, v, 4);
    return v;
}

__device__ __forceinline__ float rwSum(float v) {
    v += __shfl_xor_sync(0xffffffffu, v, 4);
    v += __shfl_xor_sync(0xffffffffu, v, 8);
    v += __shfl_xor_sync(0xffffffffu, v, 16);
    return v;
}

__device__ __forceinline__ uint32_t tf32r(float x) {
    uint32_t u;
    asm("cvt.rna.tf32.f32 %0, %1;" : "=r"(u) : "f"(x));
    return u;
}

__device__ __forceinline__ uint32_t packbf(float a, float b) {
    __nv_bfloat162 h = __floats2bfloat162_rn(a, b);
    return *(uint32_t*)&h;
}

__device__ __forceinline__ uint32_t packh(float a, float b) {
    __half2 h = __floats2half2_rn(a, b);
    return *(uint32_t*)&h;
}

// 2^t on FMA/ALU pipes (no MUFU), t <= 0 post max-subtraction.
__device__ __forceinline__ float fexp2t(float t) {
    t = fmaxf(t, -126.f);
    float m = t + 12582912.f;
    int ri = __float_as_int(m) - 0x4B400000;
    float r = m - 12582912.f;
    float f = t - r;
    float p = fmaf(9.618129e-3f, f, 5.550411e-2f);
    p = fmaf(p, f, 2.402265e-1f);
    p = fmaf(p, f, 6.931472e-1f);
    p = fmaf(p, f, 1.0f);
    return __int_as_float(__float_as_int(p) + (ri << 23));
}

__device__ __forceinline__ void mma8(float* c, const uint32_t* a, uint32_t b0, uint32_t b1) {
    asm volatile(
        "mma.sync.aligned.m16n8k8.row.col.f32.tf32.tf32.f32 "
        "{%0,%1,%2,%3},{%4,%5,%6,%7},{%8,%9},{%0,%1,%2,%3};\n"
        : "+f"(c[0]), "+f"(c[1]), "+f"(c[2]), "+f"(c[3])
        : "r"(a[0]), "r"(a[1]), "r"(a[2]), "r"(a[3]), "r"(b0), "r"(b1));
}

__device__ __forceinline__ void mma16(float* c, const uint32_t* a, uint32_t b0, uint32_t b1) {
    asm volatile(
        "mma.sync.aligned.m16n8k16.row.col.f32.bf16.bf16.f32 "
        "{%0,%1,%2,%3},{%4,%5,%6,%7},{%8,%9},{%0,%1,%2,%3};\n"
        : "+f"(c[0]), "+f"(c[1]), "+f"(c[2]), "+f"(c[3])
        : "r"(a[0]), "r"(a[1]), "r"(a[2]), "r"(a[3]), "r"(b0), "r"(b1));
}

__device__ __forceinline__ void mma16h(float* c, const uint32_t* a, uint32_t b0, uint32_t b1) {
    asm volatile(
        "mma.sync.aligned.m16n8k16.row.col.f32.f16.f16.f32 "
        "{%0,%1,%2,%3},{%4,%5,%6,%7},{%8,%9},{%0,%1,%2,%3};\n"
        : "+f"(c[0]), "+f"(c[1]), "+f"(c[2]), "+f"(c[3])
        : "r"(a[0]), "r"(a[1]), "r"(a[2]), "r"(a[3]), "r"(b0), "r"(b1));
}

// ---------------- Z: zero stat accumulators ----------------
__global__ void kZero() {
    int t = threadIdx.x;  // 512
    if (t < 96) g_simStats[t] = 0.f;
    g_outStats[t & 511] = 0.f;
    g_qkvStats[t & 511] = 0.f;
}

// ---------------- A: qkv GEMM, 8x8 thread tiles + fused BN stats ----------------
__global__ __launch_bounds__(128) void kA(const float* __restrict__ x,
                                          const float* __restrict__ W) {
    extern __shared__ float sm[];
    float* sa = sm;              // [128 k][132]
    float* sb = sm + 16896;      // [128 k][68]
    const int ot = blockIdx.x >> 1, jh = blockIdx.x & 1, bh = blockIdx.y;
    const int b0 = bh >> 6, h = bh & 63;
    const int t = threadIdx.x;

    for (int e = 0; e < 128; e++) {
        int idx = e * 128 + t;
        int r = idx >> 7, c = idx & 127;
        sa[c * 132 + r] = W[(ot * 128 + r) * 128 + c];
    }
    for (int e = 0; e < 64; e++) {
        int idx = e * 128 + t;
        int c = idx >> 6, l0 = idx & 63;
        sb[c * 68 + l0] = x[((b0 * 128 + c) * 64 + h) * 128 + jh * 64 + l0];
    }
    __syncthreads();

    const int ty = t >> 3, tx = t & 7;
    const int i0 = ty * 8, j0 = tx * 8;
    float acc[8][8];
#pragma unroll
    for (int u = 0; u < 8; u++)
#pragma unroll
        for (int v = 0; v < 8; v++) acc[u][v] = 0.f;

#pragma unroll 2
    for (int k = 0; k < 128; k++) {
        float4 A0 = *(const float4*)(sa + k * 132 + i0);
        float4 A1 = *(const float4*)(sa + k * 132 + i0 + 4);
        float4 B0 = *(const float4*)(sb + k * 68 + j0);
        float4 B1 = *(const float4*)(sb + k * 68 + j0 + 4);
        float a[8] = {A0.x, A0.y, A0.z, A0.w, A1.x, A1.y, A1.z, A1.w};
        float b[8] = {B0.x, B0.y, B0.z, B0.w, B1.x, B1.y, B1.z, B1.w};
#pragma unroll
        for (int u = 0; u < 8; u++)
#pragma unroll
            for (int v = 0; v < 8; v++) acc[u][v] += a[u] * b[v];
    }

    float* dst = g_qkv + (size_t)bh * 32768 + (size_t)(ot * 128) * 128 + jh * 64;
#pragma unroll
    for (int u = 0; u < 8; u++) {
        *(float4*)(dst + (i0 + u) * 128 + j0)     = make_float4(acc[u][0], acc[u][1], acc[u][2], acc[u][3]);
        *(float4*)(dst + (i0 + u) * 128 + j0 + 4) = make_float4(acc[u][4], acc[u][5], acc[u][6], acc[u][7]);
        float s = 0.f, s2 = 0.f;
#pragma unroll
        for (int v = 0; v < 8; v++) { s += acc[u][v]; s2 += acc[u][v] * acc[u][v]; }
        s = txSum(s);
        s2 = txSum(s2);
        if (tx == 0) {
            int ch = ot * 128 + i0 + u;
            atomicAdd(&g_qkvStats[ch * 2], s);
            atomicAdd(&g_qkvStats[ch * 2 + 1], s2);
        }
    }
}

// ---------------- C: fused qkv-BN + bf16 build + bf16 m16n8k16 qk + sim stats -------
// smem 80KB -> 2 CTAs/SM. grid (16, 128), 512 thr
__global__ __launch_bounds__(512, 2) void kC(const float* __restrict__ relemb,
                                             const float* __restrict__ gamma,
                                             const float* __restrict__ beta) {
    extern __shared__ float sm[];
    float* sreq = sm;            // [255][4]
    float* srek = sm + 1024;
    float* sq4  = sm + 2048;     // [128][4]
    float* sk4  = sm + 2560;
    uint32_t* sqe16 = (uint32_t*)(sm + 3072);    // [128 i][68 words], word = (m0,m1) bf16x2
    uint32_t* ske16 = (uint32_t*)(sm + 11776);   // [128 j][68 words]
    __shared__ float qscl[8], qsft[8];
    const int g = blockIdx.x, bh = blockIdx.y, t = threadIdx.x;
    const int lane = t & 31, w = t >> 5;

    if (t < 8) {
        int o = g * 16 + t;
        float S = g_qkvStats[o * 2], S2 = g_qkvStats[o * 2 + 1];
        float mean = S * (1.f / 16384.f);
        float var  = S2 * (1.f / 16384.f) - mean * mean;
        float sc = gamma[o] * rsqrtf(var + EPSF);
        qscl[t] = sc;
        qsft[t] = beta[o] - mean * sc;
    }
    __syncthreads();

    for (int n = t; n < 1020; n += 512) {
        int c = n & 3, d = n >> 2;
        sreq[n] = relemb[c * 255 + d];
        srek[n] = relemb[(4 + c) * 255 + d];
    }
    for (int n = t; n < 1024; n += 512) {
        int c8 = n >> 7, m = n & 127;
        int o = g * 16 + c8;
        float v = g_qkv[(size_t)bh * 32768 + o * 128 + m] * qscl[c8] + qsft[c8];
        if (c8 < 4) sq4[m * 4 + c8] = v; else sk4[m * 4 + c8 - 4] = v;
    }
    __syncthreads();

    float sQE = 0.f, sQE2 = 0.f, sKE = 0.f, sKE2 = 0.f;
    for (int e = 0; e < 16; e++) {
        int idx = e * 512 + t;
        int mh = idx >> 7;
        int i  = idx & 127;
        int m0 = mh * 2;
        float4 qa = *(const float4*)(sq4 + 4 * m0);
        float4 qb = *(const float4*)(sq4 + 4 * m0 + 4);
        float4 ka = *(const float4*)(sk4 + 4 * m0);
        float4 kb = *(const float4*)(sk4 + 4 * m0 + 4);
        int d0 = m0 - i + 127;
        float4 rq0 = *(const float4*)(sreq + 4 * d0);
        float4 rq1 = *(const float4*)(sreq + 4 * d0 + 4);
        float4 rk0 = *(const float4*)(srek + 4 * d0);
        float4 rk1 = *(const float4*)(srek + 4 * d0 + 4);
        float qe0 = qa.x * rq0.x + qa.y * rq0.y + qa.z * rq0.z + qa.w * rq0.w;
        float qe1 = qb.x * rq1.x + qb.y * rq1.y + qb.z * rq1.z + qb.w * rq1.w;
        float ke0 = ka.x * rk0.x + ka.y * rk0.y + ka.z * rk0.z + ka.w * rk0.w;
        float ke1 = kb.x * rk1.x + kb.y * rk1.y + kb.z * rk1.z + kb.w * rk1.w;
        sQE += qe0 + qe1; sQE2 += qe0 * qe0 + qe1 * qe1;
        sKE += ke0 + ke1; sKE2 += ke0 * ke0 + ke1 * ke1;
        sqe16[i * 68 + mh] = packbf(qe0, qe1);
        ske16[i * 68 + mh] = packbf(ke0, ke1);
    }
    __syncthreads();

    const int i0w = (w >> 2) * 32, j0w = (w & 3) * 32;
    const int rw = lane >> 2, cl = lane & 3;
    float c[2][4][4];
#pragma unroll
    for (int ii = 0; ii < 2; ii++)
#pragma unroll
        for (int jj = 0; jj < 4; jj++)
#pragma unroll
            for (int u = 0; u < 4; u++) c[ii][jj][u] = 0.f;

    for (int kc = 0; kc < 8; kc++) {
        const int kw = kc * 8;
        uint32_t a[2][4];
#pragma unroll
        for (int ii = 0; ii < 2; ii++) {
            const uint32_t* base = sqe16 + (i0w + ii * 16 + rw) * 68 + kw + cl;
            a[ii][0] = base[0];
            a[ii][1] = base[8 * 68];
            a[ii][2] = base[4];
            a[ii][3] = base[8 * 68 + 4];
        }
#pragma unroll
        for (int jj = 0; jj < 4; jj++) {
            const uint32_t* bb = ske16 + (j0w + jj * 8 + rw) * 68 + kw + cl;
            uint32_t b0 = bb[0];
            uint32_t b1 = bb[4];
            mma16(c[0][jj], a[0], b0, b1);
            mma16(c[1][jj], a[1], b0, b1);
        }
    }

    float sQK = 0.f, sQK2 = 0.f;
#pragma unroll
    for (int ii = 0; ii < 2; ii++)
#pragma unroll
        for (int jj = 0; jj < 4; jj++)
#pragma unroll
            for (int u = 0; u < 4; u++) { float q = c[ii][jj][u]; sQK += q; sQK2 += q * q; }

    sQK = warpSum(sQK); sQK2 = warpSum(sQK2);
    sQE = warpSum(sQE); sQE2 = warpSum(sQE2);
    sKE = warpSum(sKE); sKE2 = warpSum(sKE2);
    float* red = sq4;
    if (lane == 0) {
        red[w * 8 + 0] = sQK; red[w * 8 + 1] = sQK2;
        red[w * 8 + 2] = sQE; red[w * 8 + 3] = sQE2;
        red[w * 8 + 4] = sKE; red[w * 8 + 5] = sKE2;
    }
    __syncthreads();
    if (t < 6) {
        float tot = 0.f;
        for (int i = 0; i < 16; i++) tot += red[i * 8 + t];
        int ch = (t < 2) ? g : (t < 4) ? (16 + g) : (32 + g);
        atomicAdd(&g_simStats[ch * 2 + (t & 1)], tot);
    }
}

// ---------------- E: fp16 qe/ke (tf32-equal mantissa) -> 2 CTAs/SM -------------------
// smem 113152 B -> 2 CTAs/SM. grid (16, 128), 512 thr
__global__ __launch_bounds__(512, 2) void kE(const float* __restrict__ relemb,
                                             const float* __restrict__ gamma,
                                             const float* __restrict__ beta,
                                             const float* __restrict__ gamma_sim) {
    extern __shared__ float sm[];
    float* sreq = sm;            // [255][4]
    float* srek = sm + 1024;
    float* srva = sm + 2048;     // v rel ch 0..3 [d][4]
    float* srvb = sm + 3072;     // v rel ch 4..7 [d][4]
    float* sq4  = sm + 4096;     // [128][4]
    float* sk4  = sm + 4608;
    float* sv8  = sm + 5120;     // v all 8 ch [j][8] (tf32-rounded)
    float* schkA = sm + 6144;    // [128][4] row-chunk max
    float* schkB = sm + 6656;    // [128][4] row-chunk sum
    uint32_t* sqe16 = (uint32_t*)(sm + 7168);    // [128 i][68 words], word = fp16x2 (m-pair)
    uint32_t* ske16 = (uint32_t*)(sm + 15872);   // [128 j][68 words]
    float* ssim = sm + 7168;     // [128][133] fp32 p (aliases sqe16/ske16; written post-combine)
    float* amePart = sm + 24192; // [8 c][4 strip][128 i] (aliases ske16 tail, dead by then)
    __shared__ float qscl[16], qsft[16], sscale[3];
    const int g = blockIdx.x, bh = blockIdx.y, t = threadIdx.x;
    const int lane = t & 31, w = t >> 5;
    const int rw = lane >> 2, cl = lane & 3;

    if (t < 16) {
        int o = g * 16 + t;
        float S = g_qkvStats[o * 2], S2 = g_qkvStats[o * 2 + 1];
        float mean = S * (1.f / 16384.f);
        float var  = S2 * (1.f / 16384.f) - mean * mean;
        float sc = gamma[o] * rsqrtf(var + EPSF);
        qscl[t] = sc;
        qsft[t] = beta[o] - mean * sc;
    } else if (t < 19) {
        int idx = t - 16;
        int ch = idx * 16 + g;
        const float N = 2097152.f;
        float S = g_simStats[ch * 2], S2 = g_simStats[ch * 2 + 1];
        float mean = S / N;
        float var = S2 / N - mean * mean;
        // base-2 softmax: fold log2(e)
        sscale[idx] = gamma_sim[ch] * rsqrtf(var + EPSF) * 1.4426950408889634f;
    }
    __syncthreads();

    for (int n = t; n < 1020; n += 512) {
        int c = n & 3, d = n >> 2;
        sreq[n] = relemb[c * 255 + d];
        srek[n] = relemb[(4 + c) * 255 + d];
        srva[n] = relemb[(8 + c) * 255 + d];
        srvb[n] = relemb[(12 + c) * 255 + d];
    }
    for (int n = t; n < 2048; n += 512) {
        int c8 = n >> 7, m = n & 127;
        int o = g * 16 + c8;
        float v = g_qkv[(size_t)bh * 32768 + o * 128 + m] * qscl[c8] + qsft[c8];
        if (c8 < 4)       sq4[m * 4 + c8] = v;
        else if (c8 < 8)  sk4[m * 4 + c8 - 4] = v;
        else              sv8[m * 8 + c8 - 8] = __uint_as_float(tf32r(v));
    }
    __syncthreads();

    // build qe/ke as packed fp16 pairs (kC layout: [i][mh], word = (m0,m1))
    for (int e = 0; e < 16; e++) {
        int idx = e * 512 + t;
        int mh = idx >> 7;
        int i  = idx & 127;
        int m0 = mh * 2;
        float4 qa = *(const float4*)(sq4 + 4 * m0);
        float4 qb = *(const float4*)(sq4 + 4 * m0 + 4);
        float4 ka = *(const float4*)(sk4 + 4 * m0);
        float4 kb = *(const float4*)(sk4 + 4 * m0 + 4);
        int d0 = m0 - i + 127;
        float4 rq0 = *(const float4*)(sreq + 4 * d0);
        float4 rq1 = *(const float4*)(sreq + 4 * d0 + 4);
        float4 rk0 = *(const float4*)(srek + 4 * d0);
        float4 rk1 = *(const float4*)(srek + 4 * d0 + 4);
        float qe0 = qa.x * rq0.x + qa.y * rq0.y + qa.z * rq0.z + qa.w * rq0.w;
        float qe1 = qb.x * rq1.x + qb.y * rq1.y + qb.z * rq1.z + qb.w * rq1.w;
        float ke0 = ka.x * rk0.x + ka.y * rk0.y + ka.z * rk0.z + ka.w * rk0.w;
        float ke1 = kb.x * rk1.x + kb.y * rk1.y + kb.z * rk1.z + kb.w * rk1.w;
        sqe16[i * 68 + mh] = packh(qe0, qe1);
        ske16[i * 68 + mh] = packh(ke0, ke1);
    }
    __syncthreads();

    // qk MMA via fp16 m16n8k16 (fp16 mantissa == tf32 mantissa): 16 warps, 32x32 tiles
    const float a1 = sscale[0], a2 = sscale[1], a3 = sscale[2];
    const int i0w = (w >> 2) * 32, j0w = (w & 3) * 32;
    float c[2][4][4];
#pragma unroll
    for (int ii = 0; ii < 2; ii++)
#pragma unroll
        for (int jj = 0; jj < 4; jj++)
#pragma unroll
            for (int u = 0; u < 4; u++) c[ii][jj][u] = 0.f;

    for (int kc = 0; kc < 8; kc++) {
        const int kw = kc * 8;
        uint32_t a[2][4];
#pragma unroll
        for (int ii = 0; ii < 2; ii++) {
            const uint32_t* base = sqe16 + (i0w + ii * 16 + rw) * 68 + kw + cl;
            a[ii][0] = base[0];
            a[ii][1] = base[8 * 68];
            a[ii][2] = base[4];
            a[ii][3] = base[8 * 68 + 4];
        }
#pragma unroll
        for (int jj = 0; jj < 4; jj++) {
            const uint32_t* bb = ske16 + (j0w + jj * 8 + rw) * 68 + kw + cl;
            uint32_t b0 = bb[0];
            uint32_t b1 = bb[4];
            mma16h(c[0][jj], a[0], b0, b1);
            mma16h(c[1][jj], a[1], b0, b1);
        }
    }

    // combine: sim' = a1*qk + a2*qe + a3*ke (scales carry log2e)
    // qe(m,i) lives at word sqe16[i*68 + (m>>1)], half (m&1)
    const int hs = rw & 1;
#pragma unroll
    for (int ii = 0; ii < 2; ii++)
#pragma unroll
        for (int jj = 0; jj < 4; jj++) {
            int ir0 = i0w + ii * 16 + rw;
            int jc = j0w + jj * 8 + 2 * cl;
            int mh0 = ir0 >> 1;
            const uint32_t* q0p = sqe16 + jc * 68 + mh0;
            const uint32_t* q1p = sqe16 + (jc + 1) * 68 + mh0;
            const uint32_t* k0p = ske16 + jc * 68 + mh0;
            const uint32_t* k1p = ske16 + (jc + 1) * 68 + mh0;
            float2 qa = __half22float2(*(const __half2*)(q0p));
            float2 qb = __half22float2(*(const __half2*)(q1p));
            float2 qc = __half22float2(*(const __half2*)(q0p + 4));
            float2 qd = __half22float2(*(const __half2*)(q1p + 4));
            float2 ka = __half22float2(*(const __half2*)(k0p));
            float2 kb = __half22float2(*(const __half2*)(k1p));
            float2 kc2 = __half22float2(*(const __half2*)(k0p + 4));
            float2 kd = __half22float2(*(const __half2*)(k1p + 4));
            float* cc = c[ii][jj];
            cc[0] = a1 * cc[0] + a2 * (hs ? qa.y : qa.x) + a3 * (hs ? ka.y : ka.x);
            cc[1] = a1 * cc[1] + a2 * (hs ? qb.y : qb.x) + a3 * (hs ? kb.y : kb.x);
            cc[2] = a1 * cc[2] + a2 * (hs ? qc.y : qc.x) + a3 * (hs ? kc2.y : kc2.x);
            cc[3] = a1 * cc[3] + a2 * (hs ? qd.y : qd.x) + a3 * (hs ? kd.y : kd.x);
        }

    // ---- in-register softmax over j (base-2, FMA-pipe exp) ----
    float mx[4];
#pragma unroll
    for (int r = 0; r < 4; r++) mx[r] = -1e30f;
#pragma unroll
    for (int jj = 0; jj < 4; jj++) {
        mx[0] = fmaxf(mx[0], fmaxf(c[0][jj][0], c[0][jj][1]));
        mx[1] = fmaxf(mx[1], fmaxf(c[0][jj][2], c[0][jj][3]));
        mx[2] = fmaxf(mx[2], fmaxf(c[1][jj][0], c[1][jj][1]));
        mx[3] = fmaxf(mx[3], fmaxf(c[1][jj][2], c[1][jj][3]));
    }
#pragma unroll
    for (int o = 1; o <= 2; o <<= 1)
#pragma unroll
        for (int r = 0; r < 4; r++)
            mx[r] = fmaxf(mx[r], __shfl_xor_sync(0xffffffffu, mx[r], o));
    if (cl == 0) {
        int jt = w & 3;
        schkA[(i0w + rw) * 4 + jt]      = mx[0];
        schkA[(i0w + rw + 8) * 4 + jt]  = mx[1];
        schkA[(i0w + rw + 16) * 4 + jt] = mx[2];
        schkA[(i0w + rw + 24) * 4 + jt] = mx[3];
    }
    __syncthreads();
    float gmx[4];
#pragma unroll
    for (int r = 0; r < 4; r++) {
        float4 m4 = *(const float4*)(schkA + (i0w + rw + r * 8) * 4);
        gmx[r] = fmaxf(fmaxf(m4.x, m4.y), fmaxf(m4.z, m4.w));
    }
    float sums[4] = {0.f, 0.f, 0.f, 0.f};
#pragma unroll
    for (int jj = 0; jj < 4; jj++) {
        c[0][jj][0] = fexp2t(c[0][jj][0] - gmx[0]);
        c[0][jj][1] = fexp2t(c[0][jj][1] - gmx[0]);
        sums[0] += c[0][jj][0] + c[0][jj][1];
        c[0][jj][2] = fexp2t(c[0][jj][2] - gmx[1]);
        c[0][jj][3] = fexp2t(c[0][jj][3] - gmx[1]);
        sums[1] += c[0][jj][2] + c[0][jj][3];
        c[1][jj][0] = fexp2t(c[1][jj][0] - gmx[2]);
        c[1][jj][1] = fexp2t(c[1][jj][1] - gmx[2]);
        sums[2] += c[1][jj][0] + c[1][jj][1];
        c[1][jj][2] = fexp2t(c[1][jj][2] - gmx[3]);
        c[1][jj][3] = fexp2t(c[1][jj][3] - gmx[3]);
        sums[3] += c[1][jj][2] + c[1][jj][3];
    }
#pragma unroll
    for (int o = 1; o <= 2; o <<= 1)
#pragma unroll
        for (int r = 0; r < 4; r++)
            sums[r] += __shfl_xor_sync(0xffffffffu, sums[r], o);
    if (cl == 0) {
        int jt = w & 3;
        schkB[(i0w + rw) * 4 + jt]      = sums[0];
        schkB[(i0w + rw + 8) * 4 + jt]  = sums[1];
        schkB[(i0w + rw + 16) * 4 + jt] = sums[2];
        schkB[(i0w + rw + 24) * 4 + jt] = sums[3];
    }
    __syncthreads();
    float inv[4];
#pragma unroll
    for (int r = 0; r < 4; r++) {
        float4 s4 = *(const float4*)(schkB + (i0w + rw + r * 8) * 4);
        inv[r] = 1.f / (s4.x + s4.y + s4.z + s4.w);
    }
    // write final p (tf32-rounded) to ssim — scalar stores (pitch 133 odd)
    // safe: 2 syncthreads since last sqe16/ske16 read (combine)
#pragma unroll
    for (int ii = 0; ii < 2; ii++)
#pragma unroll
        for (int jj = 0; jj < 4; jj++) {
            int ir0 = i0w + ii * 16 + rw;
            int jc = j0w + jj * 8 + 2 * cl;
            float* cc = c[ii][jj];
            float ivl = inv[ii * 2], ivh = inv[ii * 2 + 1];
            ssim[ir0 * 133 + jc]           = __uint_as_float(tf32r(cc[0] * ivl));
            ssim[ir0 * 133 + jc + 1]       = __uint_as_float(tf32r(cc[1] * ivl));
            ssim[(ir0 + 8) * 133 + jc]     = __uint_as_float(tf32r(cc[2] * ivh));
            ssim[(ir0 + 8) * 133 + jc + 1] = __uint_as_float(tf32r(cc[3] * ivh));
        }
    __syncthreads();

    // ame strips: thread owns (i, strip of 32 j), all 8 channels -> partials to smem
    {
        const int i = t & 127, s = t >> 7;
        float accE[8] = {0.f, 0.f, 0.f, 0.f, 0.f, 0.f, 0.f, 0.f};
        const int jb = s * 32;
        for (int jj = 0; jj < 32; jj++) {
            int j = jb + jj;
            float p = ssim[i * 133 + j];
            int d = i - j + 127;
            float4 ra = *(const float4*)(srva + 4 * d);
            float4 rb = *(const float4*)(srvb + 4 * d);
            accE[0] += p * ra.x; accE[1] += p * ra.y; accE[2] += p * ra.z; accE[3] += p * ra.w;
            accE[4] += p * rb.x; accE[5] += p * rb.y; accE[6] += p * rb.z; accE[7] += p * rb.w;
        }
        // amePart disjoint from ssim; ske16 region dead since combine — no barrier needed
#pragma unroll
        for (int ch = 0; ch < 8; ch++)
            amePart[ch * 512 + s * 128 + i] = accE[ch];
    }
    __syncthreads();

    float* dst = g_outraw + (size_t)bh * 32768;
    if (w < 8) {
        // am via tf32 MMA: A = P (ssim, pre-rounded), B = v (sv8, pre-rounded)
        const int i0 = w * 16;
        float ca[4] = {0.f, 0.f, 0.f, 0.f};
        for (int kc = 0; kc < 16; kc++) {
            const int k0 = kc * 8;
            const float* pr0 = ssim + (i0 + rw) * 133 + k0 + cl;
            const float* pr1 = pr0 + 8 * 133;
            uint32_t a[4];
            a[0] = __float_as_uint(pr0[0]);
            a[1] = __float_as_uint(pr1[0]);
            a[2] = __float_as_uint(pr0[4]);
            a[3] = __float_as_uint(pr1[4]);
            uint32_t b0 = __float_as_uint(sv8[(k0 + cl) * 8 + rw]);
            uint32_t b1 = __float_as_uint(sv8[(k0 + cl + 4) * 8 + rw]);
            mma8(ca, a, b0, b1);
        }
        const int i1 = i0 + rw, i2 = i0 + rw + 8;
        const int ch0 = 2 * cl, ch1 = 2 * cl + 1;
        const int o0 = g * 16 + 2 * ch0, o1 = g * 16 + 2 * ch1;
        dst[o0 * 128 + i1] = ca[0];
        dst[o1 * 128 + i1] = ca[1];
        dst[o0 * 128 + i2] = ca[2];
        dst[o1 * 128 + i2] = ca[3];
        float s0 = ca[0] + ca[2], s02 = ca[0] * ca[0] + ca[2] * ca[2];
        float s1 = ca[1] + ca[3], s12 = ca[1] * ca[1] + ca[3] * ca[3];
        s0 = rwSum(s0); s02 = rwSum(s02); s1 = rwSum(s1); s12 = rwSum(s12);
        if (rw == 0) {
            atomicAdd(&g_outStats[o0 * 2], s0);
            atomicAdd(&g_outStats[o0 * 2 + 1], s02);
            atomicAdd(&g_outStats[o1 * 2], s1);
            atomicAdd(&g_outStats[o1 * 2 + 1], s12);
        }
    } else {
        // ame reduce: warp handles one channel; lane covers 4 consecutive i
        const int ch = w - 8;
        const int iB = lane * 4;
        float4 v0 = *(const float4*)(amePart + ch * 512 + 0 * 128 + iB);
        float4 v1 = *(const float4*)(amePart + ch * 512 + 1 * 128 + iB);
        float4 v2 = *(const float4*)(amePart + ch * 512 + 2 * 128 + iB);
        float4 v3 = *(const float4*)(amePart + ch * 512 + 3 * 128 + iB);
        float4 r4 = make_float4(v0.x + v1.x + v2.x + v3.x,
                                v0.y + v1.y + v2.y + v3.y,
                                v0.z + v1.z + v2.z + v3.z,
                                v0.w + v1.w + v2.w + v3.w);
        const int o = g * 16 + 2 * ch + 1;
        *(float4*)(dst + o * 128 + iB) = r4;
        float sE = r4.x + r4.y + r4.z + r4.w;
        float sE2 = r4.x * r4.x + r4.y * r4.y + r4.z * r4.z + r4.w * r4.w;
        sE = warpSum(sE); sE2 = warpSum(sE2);
        if (lane == 0) {
            atomicAdd(&g_outStats[o * 2], sE);
            atomicAdd(&g_outStats[o * 2 + 1], sE2);
        }
    }
}

// ---------------- F: finalize out BN params ----------------
__global__ void kF(const float* __restrict__ gamma_out, const float* __restrict__ beta_out) {
    int o = threadIdx.x;  // 256
    const float N = 16384.f;
    float S = g_outStats[o * 2], S2 = g_outStats[o * 2 + 1];
    float mean = S / N;
    float var = S2 / N - mean * mean;
    float sc = gamma_out[o] * rsqrtf(var + EPSF);
    g_outScale[o] = sc;
    g_outShift[o] = beta_out[o] - mean * sc;
}

// ---------------- G: y = bn(out)[2oc] + bn(out)[2oc+1] ----------------
__global__ __launch_bounds__(256) void kG(float* __restrict__ y) {
    int idx = blockIdx.x * 256 + threadIdx.x;
    int wpos = idx & 127;
    int h = (idx >> 7) & 63;
    int oc = (idx >> 13) & 127;
    int b0 = idx >> 20;
    int bh = b0 * 64 + h;
    int o = oc * 2;
    float v0 = g_outraw[(size_t)bh * 32768 + o * 128 + wpos];
    float v1 = g_outraw[(size_t)bh * 32768 + (o + 1) * 128 + wpos];
    y[idx] = (v0 * g_outScale[o] + g_outShift[o]) + (v1 * g_outScale[o + 1] + g_outShift[o + 1]);
}

// ---------------- launch ----------------
extern "C" void kernel_launch(void* const* d_in, const int* in_sizes, int n_in,
                              void* d_out, int out_size) {
    const float* x  = (const float*)d_in[0];
    const float* W  = (const float*)d_in[1];
    const float* gq = (const float*)d_in[2];
    const float* bq = (const float*)d_in[3];
    const float* re = (const float*)d_in[4];
    const float* gs = (const float*)d_in[5];
    // beta_sim (d_in[6]) cancels inside softmax — unused
    const float* go = (const float*)d_in[7];
    const float* bo = (const float*)d_in[8];
    float* y = (float*)d_out;

    const int SMEM_A = (16896 + 128 * 68) * 4;       // 102400
    const int SMEM_C = 20480 * 4;                    // 81920 -> 2 CTAs/SM
    const int SMEM_E = 28288 * 4;                    // 113152 -> 2 CTAs/SM

    cudaFuncSetAttribute(kA, cudaFuncAttributeMaxDynamicSharedMemorySize, SMEM_A);
    cudaFuncSetAttribute(kC, cudaFuncAttributeMaxDynamicSharedMemorySize, SMEM_C);
    cudaFuncSetAttribute(kE, cudaFuncAttributeMaxDynamicSharedMemorySize, SMEM_E);

    kZero<<<1, 512>>>();
    kA<<<dim3(4, 128), 128, SMEM_A>>>(x, W);
    kC<<<dim3(16, 128), 512, SMEM_C>>>(re, gq, bq);
    kE<<<dim3(16, 128), 512, SMEM_E>>>(re, gq, bq, gs);
    kF<<<1, 256>>>(go, bo);
    kG<<<8192, 256>>>(y);
}

// round 17
// speedup vs baseline: 1.1700x; 1.0558x over previous
#include <cuda_runtime.h>
#include <cuda_bf16.h>
#include <cuda_fp16.h>
#include <math.h>
#include <stdint.h>

#define EPSF 1e-5f

// ---------------- scratch (device globals) ----------------
__device__ float g_qkv[4194304];      // [128 bh][256 o][128 l]
__device__ float g_outraw[4194304];   // [128 bh][256 o][128 i]
__device__ float g_qkvStats[512];     // [256 ch][sum,sumsq]
__device__ float g_simStats[96];
__device__ float g_outStats[512];

__device__ __forceinline__ float warpSum(float v) {
#pragma unroll
    for (int o = 16; o > 0; o >>= 1) v += __shfl_xor_sync(0xffffffffu, v, o);
    return v;
}

__device__ __forceinline__ float txSum(float v) {
    v += __shfl_xor_sync(0xffffffffu, v, 1);
    v += __shfl_xor_sync(0xffffffffu, v, 2);
    v += __shfl_xor_sync(0xffffffffu, v, 4);
    return v;
}

__device__ __forceinline__ float rwSum(float v) {
    v += __shfl_xor_sync(0xffffffffu, v, 4);
    v += __shfl_xor_sync(0xffffffffu, v, 8);
    v += __shfl_xor_sync(0xffffffffu, v, 16);
    return v;
}

__device__ __forceinline__ uint32_t tf32r(float x) {
    uint32_t u;
    asm("cvt.rna.tf32.f32 %0, %1;" : "=r"(u) : "f"(x));
    return u;
}

__device__ __forceinline__ uint32_t packbf(float a, float b) {
    __nv_bfloat162 h = __floats2bfloat162_rn(a, b);
    return *(uint32_t*)&h;
}

__device__ __forceinline__ uint32_t packh(float a, float b) {
    __half2 h = __floats2half2_rn(a, b);
    return *(uint32_t*)&h;
}

// 2^t on FMA/ALU pipes (no MUFU), t <= 0 post max-subtraction.
__device__ __forceinline__ float fexp2t(float t) {
    t = fmaxf(t, -126.f);
    float m = t + 12582912.f;
    int ri = __float_as_int(m) - 0x4B400000;
    float r = m - 12582912.f;
    float f = t - r;
    float p = fmaf(9.618129e-3f, f, 5.550411e-2f);
    p = fmaf(p, f, 2.402265e-1f);
    p = fmaf(p, f, 6.931472e-1f);
    p = fmaf(p, f, 1.0f);
    return __int_as_float(__float_as_int(p) + (ri << 23));
}

__device__ __forceinline__ void mma8(float* c, const uint32_t* a, uint32_t b0, uint32_t b1) {
    asm volatile(
        "mma.sync.aligned.m16n8k8.row.col.f32.tf32.tf32.f32 "
        "{%0,%1,%2,%3},{%4,%5,%6,%7},{%8,%9},{%0,%1,%2,%3};\n"
        : "+f"(c[0]), "+f"(c[1]), "+f"(c[2]), "+f"(c[3])
        : "r"(a[0]), "r"(a[1]), "r"(a[2]), "r"(a[3]), "r"(b0), "r"(b1));
}

__device__ __forceinline__ void mma16(float* c, const uint32_t* a, uint32_t b0, uint32_t b1) {
    asm volatile(
        "mma.sync.aligned.m16n8k16.row.col.f32.bf16.bf16.f32 "
        "{%0,%1,%2,%3},{%4,%5,%6,%7},{%8,%9},{%0,%1,%2,%3};\n"
        : "+f"(c[0]), "+f"(c[1]), "+f"(c[2]), "+f"(c[3])
        : "r"(a[0]), "r"(a[1]), "r"(a[2]), "r"(a[3]), "r"(b0), "r"(b1));
}

__device__ __forceinline__ void mma16h(float* c, const uint32_t* a, uint32_t b0, uint32_t b1) {
    asm volatile(
        "mma.sync.aligned.m16n8k16.row.col.f32.f16.f16.f32 "
        "{%0,%1,%2,%3},{%4,%5,%6,%7},{%8,%9},{%0,%1,%2,%3};\n"
        : "+f"(c[0]), "+f"(c[1]), "+f"(c[2]), "+f"(c[3])
        : "r"(a[0]), "r"(a[1]), "r"(a[2]), "r"(a[3]), "r"(b0), "r"(b1));
}

// ---------------- Z: zero stat accumulators ----------------
__global__ void kZero() {
    int t = threadIdx.x;  // 512
    if (t < 96) g_simStats[t] = 0.f;
    g_outStats[t & 511] = 0.f;
    g_qkvStats[t & 511] = 0.f;
}

// ---------------- A: qkv GEMM, 8x8 thread tiles + fused BN stats ----------------
__global__ __launch_bounds__(128) void kA(const float* __restrict__ x,
                                          const float* __restrict__ W) {
    extern __shared__ float sm[];
    float* sa = sm;              // [128 k][132]
    float* sb = sm + 16896;      // [128 k][68]
    const int ot = blockIdx.x >> 1, jh = blockIdx.x & 1, bh = blockIdx.y;
    const int b0 = bh >> 6, h = bh & 63;
    const int t = threadIdx.x;

    for (int e = 0; e < 128; e++) {
        int idx = e * 128 + t;
        int r = idx >> 7, c = idx & 127;
        sa[c * 132 + r] = W[(ot * 128 + r) * 128 + c];
    }
    for (int e = 0; e < 64; e++) {
        int idx = e * 128 + t;
        int c = idx >> 6, l0 = idx & 63;
        sb[c * 68 + l0] = x[((b0 * 128 + c) * 64 + h) * 128 + jh * 64 + l0];
    }
    __syncthreads();

    const int ty = t >> 3, tx = t & 7;
    const int i0 = ty * 8, j0 = tx * 8;
    float acc[8][8];
#pragma unroll
    for (int u = 0; u < 8; u++)
#pragma unroll
        for (int v = 0; v < 8; v++) acc[u][v] = 0.f;

#pragma unroll 2
    for (int k = 0; k < 128; k++) {
        float4 A0 = *(const float4*)(sa + k * 132 + i0);
        float4 A1 = *(const float4*)(sa + k * 132 + i0 + 4);
        float4 B0 = *(const float4*)(sb + k * 68 + j0);
        float4 B1 = *(const float4*)(sb + k * 68 + j0 + 4);
        float a[8] = {A0.x, A0.y, A0.z, A0.w, A1.x, A1.y, A1.z, A1.w};
        float b[8] = {B0.x, B0.y, B0.z, B0.w, B1.x, B1.y, B1.z, B1.w};
#pragma unroll
        for (int u = 0; u < 8; u++)
#pragma unroll
            for (int v = 0; v < 8; v++) acc[u][v] += a[u] * b[v];
    }

    float* dst = g_qkv + (size_t)bh * 32768 + (size_t)(ot * 128) * 128 + jh * 64;
#pragma unroll
    for (int u = 0; u < 8; u++) {
        *(float4*)(dst + (i0 + u) * 128 + j0)     = make_float4(acc[u][0], acc[u][1], acc[u][2], acc[u][3]);
        *(float4*)(dst + (i0 + u) * 128 + j0 + 4) = make_float4(acc[u][4], acc[u][5], acc[u][6], acc[u][7]);
        float s = 0.f, s2 = 0.f;
#pragma unroll
        for (int v = 0; v < 8; v++) { s += acc[u][v]; s2 += acc[u][v] * acc[u][v]; }
        s = txSum(s);
        s2 = txSum(s2);
        if (tx == 0) {
            int ch = ot * 128 + i0 + u;
            atomicAdd(&g_qkvStats[ch * 2], s);
            atomicAdd(&g_qkvStats[ch * 2 + 1], s2);
        }
    }
}

// ---------------- C: fused qkv-BN + bf16 build + bf16 m16n8k16 qk + sim stats -------
// smem 80KB -> 2 CTAs/SM. grid (16, 128), 512 thr
__global__ __launch_bounds__(512, 2) void kC(const float* __restrict__ relemb,
                                             const float* __restrict__ gamma,
                                             const float* __restrict__ beta) {
    extern __shared__ float sm[];
    float* sreq = sm;            // [255][4]
    float* srek = sm + 1024;
    float* sq4  = sm + 2048;     // [128][4]
    float* sk4  = sm + 2560;
    uint32_t* sqe16 = (uint32_t*)(sm + 3072);    // [128 i][68 words], word = (m0,m1) bf16x2
    uint32_t* ske16 = (uint32_t*)(sm + 11776);   // [128 j][68 words]
    __shared__ float qscl[8], qsft[8];
    const int g = blockIdx.x, bh = blockIdx.y, t = threadIdx.x;
    const int lane = t & 31, w = t >> 5;

    if (t < 8) {
        int o = g * 16 + t;
        float S = g_qkvStats[o * 2], S2 = g_qkvStats[o * 2 + 1];
        float mean = S * (1.f / 16384.f);
        float var  = S2 * (1.f / 16384.f) - mean * mean;
        float sc = gamma[o] * rsqrtf(var + EPSF);
        qscl[t] = sc;
        qsft[t] = beta[o] - mean * sc;
    }
    __syncthreads();

    for (int n = t; n < 1020; n += 512) {
        int c = n & 3, d = n >> 2;
        sreq[n] = relemb[c * 255 + d];
        srek[n] = relemb[(4 + c) * 255 + d];
    }
    for (int n = t; n < 1024; n += 512) {
        int c8 = n >> 7, m = n & 127;
        int o = g * 16 + c8;
        float v = g_qkv[(size_t)bh * 32768 + o * 128 + m] * qscl[c8] + qsft[c8];
        if (c8 < 4) sq4[m * 4 + c8] = v; else sk4[m * 4 + c8 - 4] = v;
    }
    __syncthreads();

    float sQE = 0.f, sQE2 = 0.f, sKE = 0.f, sKE2 = 0.f;
    for (int e = 0; e < 16; e++) {
        int idx = e * 512 + t;
        int mh = idx >> 7;
        int i  = idx & 127;
        int m0 = mh * 2;
        float4 qa = *(const float4*)(sq4 + 4 * m0);
        float4 qb = *(const float4*)(sq4 + 4 * m0 + 4);
        float4 ka = *(const float4*)(sk4 + 4 * m0);
        float4 kb = *(const float4*)(sk4 + 4 * m0 + 4);
        int d0 = m0 - i + 127;
        float4 rq0 = *(const float4*)(sreq + 4 * d0);
        float4 rq1 = *(const float4*)(sreq + 4 * d0 + 4);
        float4 rk0 = *(const float4*)(srek + 4 * d0);
        float4 rk1 = *(const float4*)(srek + 4 * d0 + 4);
        float qe0 = qa.x * rq0.x + qa.y * rq0.y + qa.z * rq0.z + qa.w * rq0.w;
        float qe1 = qb.x * rq1.x + qb.y * rq1.y + qb.z * rq1.z + qb.w * rq1.w;
        float ke0 = ka.x * rk0.x + ka.y * rk0.y + ka.z * rk0.z + ka.w * rk0.w;
        float ke1 = kb.x * rk1.x + kb.y * rk1.y + kb.z * rk1.z + kb.w * rk1.w;
        sQE += qe0 + qe1; sQE2 += qe0 * qe0 + qe1 * qe1;
        sKE += ke0 + ke1; sKE2 += ke0 * ke0 + ke1 * ke1;
        sqe16[i * 68 + mh] = packbf(qe0, qe1);
        ske16[i * 68 + mh] = packbf(ke0, ke1);
    }
    __syncthreads();

    const int i0w = (w >> 2) * 32, j0w = (w & 3) * 32;
    const int rw = lane >> 2, cl = lane & 3;
    float c[2][4][4];
#pragma unroll
    for (int ii = 0; ii < 2; ii++)
#pragma unroll
        for (int jj = 0; jj < 4; jj++)
#pragma unroll
            for (int u = 0; u < 4; u++) c[ii][jj][u] = 0.f;

    for (int kc = 0; kc < 8; kc++) {
        const int kw = kc * 8;
        uint32_t a[2][4];
#pragma unroll
        for (int ii = 0; ii < 2; ii++) {
            const uint32_t* base = sqe16 + (i0w + ii * 16 + rw) * 68 + kw + cl;
            a[ii][0] = base[0];
            a[ii][1] = base[8 * 68];
            a[ii][2] = base[4];
            a[ii][3] = base[8 * 68 + 4];
        }
#pragma unroll
        for (int jj = 0; jj < 4; jj++) {
            const uint32_t* bb = ske16 + (j0w + jj * 8 + rw) * 68 + kw + cl;
            uint32_t b0 = bb[0];
            uint32_t b1 = bb[4];
            mma16(c[0][jj], a[0], b0, b1);
            mma16(c[1][jj], a[1], b0, b1);
        }
    }

    float sQK = 0.f, sQK2 = 0.f;
#pragma unroll
    for (int ii = 0; ii < 2; ii++)
#pragma unroll
        for (int jj = 0; jj < 4; jj++)
#pragma unroll
            for (int u = 0; u < 4; u++) { float q = c[ii][jj][u]; sQK += q; sQK2 += q * q; }

    sQK = warpSum(sQK); sQK2 = warpSum(sQK2);
    sQE = warpSum(sQE); sQE2 = warpSum(sQE2);
    sKE = warpSum(sKE); sKE2 = warpSum(sKE2);
    float* red = sq4;
    if (lane == 0) {
        red[w * 8 + 0] = sQK; red[w * 8 + 1] = sQK2;
        red[w * 8 + 2] = sQE; red[w * 8 + 3] = sQE2;
        red[w * 8 + 4] = sKE; red[w * 8 + 5] = sKE2;
    }
    __syncthreads();
    if (t < 6) {
        float tot = 0.f;
        for (int i = 0; i < 16; i++) tot += red[i * 8 + t];
        int ch = (t < 2) ? g : (t < 4) ? (16 + g) : (32 + g);
        atomicAdd(&g_simStats[ch * 2 + (t & 1)], tot);
    }
}

// ---------------- E: fp16 qe/ke + fp16 rel_v tables, 2 CTAs/SM -----------------------
// grid (16, 128), 512 thr
__global__ __launch_bounds__(512, 2) void kE(const float* __restrict__ relemb,
                                             const float* __restrict__ gamma,
                                             const float* __restrict__ beta,
                                             const float* __restrict__ gamma_sim) {
    extern __shared__ float sm[];
    float* sreq = sm;            // [255][4]
    float* srek = sm + 1024;
    uint32_t* srv16 = (uint32_t*)(sm + 2048);    // [255 d][4 words]: ch (0,1)(2,3)(4,5)(6,7) fp16x2
    float* sq4  = sm + 4096;     // [128][4]
    float* sk4  = sm + 4608;
    float* sv8  = sm + 5120;     // v all 8 ch [j][8] (tf32-rounded)
    float* schkA = sm + 6144;    // [128][4] row-chunk max
    float* schkB = sm + 6656;    // [128][4] row-chunk sum
    uint32_t* sqe16 = (uint32_t*)(sm + 7168);    // [128 i][68 words], word = fp16x2 (m-pair)
    uint32_t* ske16 = (uint32_t*)(sm + 15872);   // [128 j][68 words]
    float* ssim = sm + 7168;     // [128][133] fp32 p (aliases sqe16/ske16; written post-combine)
    float* amePart = sm + 24192; // [8 c][4 strip][128 i] (aliases ske16 tail, dead by then)
    __shared__ float qscl[16], qsft[16], sscale[3];
    const int g = blockIdx.x, bh = blockIdx.y, t = threadIdx.x;
    const int lane = t & 31, w = t >> 5;
    const int rw = lane >> 2, cl = lane & 3;

    if (t < 16) {
        int o = g * 16 + t;
        float S = g_qkvStats[o * 2], S2 = g_qkvStats[o * 2 + 1];
        float mean = S * (1.f / 16384.f);
        float var  = S2 * (1.f / 16384.f) - mean * mean;
        float sc = gamma[o] * rsqrtf(var + EPSF);
        qscl[t] = sc;
        qsft[t] = beta[o] - mean * sc;
    } else if (t < 19) {
        int idx = t - 16;
        int ch = idx * 16 + g;
        const float N = 2097152.f;
        float S = g_simStats[ch * 2], S2 = g_simStats[ch * 2 + 1];
        float mean = S / N;
        float var = S2 / N - mean * mean;
        // base-2 softmax: fold log2(e)
        sscale[idx] = gamma_sim[ch] * rsqrtf(var + EPSF) * 1.4426950408889634f;
    }
    __syncthreads();

    for (int n = t; n < 1020; n += 512) {
        int c = n & 3, d = n >> 2;
        sreq[n] = relemb[c * 255 + d];
        srek[n] = relemb[(4 + c) * 255 + d];
        // rel_v channels (2c, 2c+1) packed fp16
        srv16[d * 4 + c] = packh(relemb[(8 + 2 * c) * 255 + d], relemb[(9 + 2 * c) * 255 + d]);
    }
    for (int n = t; n < 2048; n += 512) {
        int c8 = n >> 7, m = n & 127;
        int o = g * 16 + c8;
        float v = g_qkv[(size_t)bh * 32768 + o * 128 + m] * qscl[c8] + qsft[c8];
        if (c8 < 4)       sq4[m * 4 + c8] = v;
        else if (c8 < 8)  sk4[m * 4 + c8 - 4] = v;
        else              sv8[m * 8 + c8 - 8] = __uint_as_float(tf32r(v));
    }
    __syncthreads();

    // build qe/ke as packed fp16 pairs (kC layout: [i][mh], word = (m0,m1))
    for (int e = 0; e < 16; e++) {
        int idx = e * 512 + t;
        int mh = idx >> 7;
        int i  = idx & 127;
        int m0 = mh * 2;
        float4 qa = *(const float4*)(sq4 + 4 * m0);
        float4 qb = *(const float4*)(sq4 + 4 * m0 + 4);
        float4 ka = *(const float4*)(sk4 + 4 * m0);
        float4 kb = *(const float4*)(sk4 + 4 * m0 + 4);
        int d0 = m0 - i + 127;
        float4 rq0 = *(const float4*)(sreq + 4 * d0);
        float4 rq1 = *(const float4*)(sreq + 4 * d0 + 4);
        float4 rk0 = *(const float4*)(srek + 4 * d0);
        float4 rk1 = *(const float4*)(srek + 4 * d0 + 4);
        float qe0 = qa.x * rq0.x + qa.y * rq0.y + qa.z * rq0.z + qa.w * rq0.w;
        float qe1 = qb.x * rq1.x + qb.y * rq1.y + qb.z * rq1.z + qb.w * rq1.w;
        float ke0 = ka.x * rk0.x + ka.y * rk0.y + ka.z * rk0.z + ka.w * rk0.w;
        float ke1 = kb.x * rk1.x + kb.y * rk1.y + kb.z * rk1.z + kb.w * rk1.w;
        sqe16[i * 68 + mh] = packh(qe0, qe1);
        ske16[i * 68 + mh] = packh(ke0, ke1);
    }
    __syncthreads();

    // qk MMA via fp16 m16n8k16: 16 warps, 32x32 tiles
    const float a1 = sscale[0], a2 = sscale[1], a3 = sscale[2];
    const int i0w = (w >> 2) * 32, j0w = (w & 3) * 32;
    float c[2][4][4];
#pragma unroll
    for (int ii = 0; ii < 2; ii++)
#pragma unroll
        for (int jj = 0; jj < 4; jj++)
#pragma unroll
            for (int u = 0; u < 4; u++) c[ii][jj][u] = 0.f;

    for (int kc = 0; kc < 8; kc++) {
        const int kw = kc * 8;
        uint32_t a[2][4];
#pragma unroll
        for (int ii = 0; ii < 2; ii++) {
            const uint32_t* base = sqe16 + (i0w + ii * 16 + rw) * 68 + kw + cl;
            a[ii][0] = base[0];
            a[ii][1] = base[8 * 68];
            a[ii][2] = base[4];
            a[ii][3] = base[8 * 68 + 4];
        }
#pragma unroll
        for (int jj = 0; jj < 4; jj++) {
            const uint32_t* bb = ske16 + (j0w + jj * 8 + rw) * 68 + kw + cl;
            uint32_t b0 = bb[0];
            uint32_t b1 = bb[4];
            mma16h(c[0][jj], a[0], b0, b1);
            mma16h(c[1][jj], a[1], b0, b1);
        }
    }

    // combine: sim' = a1*qk + a2*qe + a3*ke (scales carry log2e)
    const int hs = rw & 1;
#pragma unroll
    for (int ii = 0; ii < 2; ii++)
#pragma unroll
        for (int jj = 0; jj < 4; jj++) {
            int ir0 = i0w + ii * 16 + rw;
            int jc = j0w + jj * 8 + 2 * cl;
            int mh0 = ir0 >> 1;
            const uint32_t* q0p = sqe16 + jc * 68 + mh0;
            const uint32_t* q1p = sqe16 + (jc + 1) * 68 + mh0;
            const uint32_t* k0p = ske16 + jc * 68 + mh0;
            const uint32_t* k1p = ske16 + (jc + 1) * 68 + mh0;
            float2 qa = __half22float2(*(const __half2*)(q0p));
            float2 qb = __half22float2(*(const __half2*)(q1p));
            float2 qc = __half22float2(*(const __half2*)(q0p + 4));
            float2 qd = __half22float2(*(const __half2*)(q1p + 4));
            float2 ka = __half22float2(*(const __half2*)(k0p));
            float2 kb = __half22float2(*(const __half2*)(k1p));
            float2 kc2 = __half22float2(*(const __half2*)(k0p + 4));
            float2 kd = __half22float2(*(const __half2*)(k1p + 4));
            float* cc = c[ii][jj];
            cc[0] = a1 * cc[0] + a2 * (hs ? qa.y : qa.x) + a3 * (hs ? ka.y : ka.x);
            cc[1] = a1 * cc[1] + a2 * (hs ? qb.y : qb.x) + a3 * (hs ? kb.y : kb.x);
            cc[2] = a1 * cc[2] + a2 * (hs ? qc.y : qc.x) + a3 * (hs ? kc2.y : kc2.x);
            cc[3] = a1 * cc[3] + a2 * (hs ? qd.y : qd.x) + a3 * (hs ? kd.y : kd.x);
        }

    // ---- in-register softmax over j (base-2, FMA-pipe exp) ----
    float mx[4];
#pragma unroll
    for (int r = 0; r < 4; r++) mx[r] = -1e30f;
#pragma unroll
    for (int jj = 0; jj < 4; jj++) {
        mx[0] = fmaxf(mx[0], fmaxf(c[0][jj][0], c[0][jj][1]));
        mx[1] = fmaxf(mx[1], fmaxf(c[0][jj][2], c[0][jj][3]));
        mx[2] = fmaxf(mx[2], fmaxf(c[1][jj][0], c[1][jj][1]));
        mx[3] = fmaxf(mx[3], fmaxf(c[1][jj][2], c[1][jj][3]));
    }
#pragma unroll
    for (int o = 1; o <= 2; o <<= 1)
#pragma unroll
        for (int r = 0; r < 4; r++)
            mx[r] = fmaxf(mx[r], __shfl_xor_sync(0xffffffffu, mx[r], o));
    if (cl == 0) {
        int jt = w & 3;
        schkA[(i0w + rw) * 4 + jt]      = mx[0];
        schkA[(i0w + rw + 8) * 4 + jt]  = mx[1];
        schkA[(i0w + rw + 16) * 4 + jt] = mx[2];
        schkA[(i0w + rw + 24) * 4 + jt] = mx[3];
    }
    __syncthreads();
    float gmx[4];
#pragma unroll
    for (int r = 0; r < 4; r++) {
        float4 m4 = *(const float4*)(schkA + (i0w + rw + r * 8) * 4);
        gmx[r] = fmaxf(fmaxf(m4.x, m4.y), fmaxf(m4.z, m4.w));
    }
    float sums[4] = {0.f, 0.f, 0.f, 0.f};
#pragma unroll
    for (int jj = 0; jj < 4; jj++) {
        c[0][jj][0] = fexp2t(c[0][jj][0] - gmx[0]);
        c[0][jj][1] = fexp2t(c[0][jj][1] - gmx[0]);
        sums[0] += c[0][jj][0] + c[0][jj][1];
        c[0][jj][2] = fexp2t(c[0][jj][2] - gmx[1]);
        c[0][jj][3] = fexp2t(c[0][jj][3] - gmx[1]);
        sums[1] += c[0][jj][2] + c[0][jj][3];
        c[1][jj][0] = fexp2t(c[1][jj][0] - gmx[2]);
        c[1][jj][1] = fexp2t(c[1][jj][1] - gmx[2]);
        sums[2] += c[1][jj][0] + c[1][jj][1];
        c[1][jj][2] = fexp2t(c[1][jj][2] - gmx[3]);
        c[1][jj][3] = fexp2t(c[1][jj][3] - gmx[3]);
        sums[3] += c[1][jj][2] + c[1][jj][3];
    }
#pragma unroll
    for (int o = 1; o <= 2; o <<= 1)
#pragma unroll
        for (int r = 0; r < 4; r++)
            sums[r] += __shfl_xor_sync(0xffffffffu, sums[r], o);
    if (cl == 0) {
        int jt = w & 3;
        schkB[(i0w + rw) * 4 + jt]      = sums[0];
        schkB[(i0w + rw + 8) * 4 + jt]  = sums[1];
        schkB[(i0w + rw + 16) * 4 + jt] = sums[2];
        schkB[(i0w + rw + 24) * 4 + jt] = sums[3];
    }
    __syncthreads();
    float inv[4];
#pragma unroll
    for (int r = 0; r < 4; r++) {
        float4 s4 = *(const float4*)(schkB + (i0w + rw + r * 8) * 4);
        inv[r] = 1.f / (s4.x + s4.y + s4.z + s4.w);
    }
    // write final p (tf32-rounded) to ssim — scalar stores (pitch 133 odd)
#pragma unroll
    for (int ii = 0; ii < 2; ii++)
#pragma unroll
        for (int jj = 0; jj < 4; jj++) {
            int ir0 = i0w + ii * 16 + rw;
            int jc = j0w + jj * 8 + 2 * cl;
            float* cc = c[ii][jj];
            float ivl = inv[ii * 2], ivh = inv[ii * 2 + 1];
            ssim[ir0 * 133 + jc]           = __uint_as_float(tf32r(cc[0] * ivl));
            ssim[ir0 * 133 + jc + 1]       = __uint_as_float(tf32r(cc[1] * ivl));
            ssim[(ir0 + 8) * 133 + jc]     = __uint_as_float(tf32r(cc[2] * ivh));
            ssim[(ir0 + 8) * 133 + jc + 1] = __uint_as_float(tf32r(cc[3] * ivh));
        }
    __syncthreads();

    // ame strips: thread owns (i, strip of 32 j), all 8 channels via one uint4 fp16 load
    {
        const int i = t & 127, s = t >> 7;
        float accE[8] = {0.f, 0.f, 0.f, 0.f, 0.f, 0.f, 0.f, 0.f};
        const int jb = s * 32;
        for (int jj = 0; jj < 32; jj++) {
            int j = jb + jj;
            float p = ssim[i * 133 + j];
            int d = i - j + 127;
            uint4 rv = *(const uint4*)(srv16 + 4 * d);
            float2 r01 = __half22float2(*(const __half2*)&rv.x);
            float2 r23 = __half22float2(*(const __half2*)&rv.y);
            float2 r45 = __half22float2(*(const __half2*)&rv.z);
            float2 r67 = __half22float2(*(const __half2*)&rv.w);
            accE[0] += p * r01.x; accE[1] += p * r01.y;
            accE[2] += p * r23.x; accE[3] += p * r23.y;
            accE[4] += p * r45.x; accE[5] += p * r45.y;
            accE[6] += p * r67.x; accE[7] += p * r67.y;
        }
        // amePart disjoint from ssim; ske16 region dead since combine — no barrier needed
#pragma unroll
        for (int ch = 0; ch < 8; ch++)
            amePart[ch * 512 + s * 128 + i] = accE[ch];
    }
    __syncthreads();

    float* dst = g_outraw + (size_t)bh * 32768;
    if (w < 8) {
        // am via tf32 MMA: A = P (ssim, pre-rounded), B = v (sv8, pre-rounded)
        const int i0 = w * 16;
        float ca[4] = {0.f, 0.f, 0.f, 0.f};
        for (int kc = 0; kc < 16; kc++) {
            const int k0 = kc * 8;
            const float* pr0 = ssim + (i0 + rw) * 133 + k0 + cl;
            const float* pr1 = pr0 + 8 * 133;
            uint32_t a[4];
            a[0] = __float_as_uint(pr0[0]);
            a[1] = __float_as_uint(pr1[0]);
            a[2] = __float_as_uint(pr0[4]);
            a[3] = __float_as_uint(pr1[4]);
            uint32_t b0 = __float_as_uint(sv8[(k0 + cl) * 8 + rw]);
            uint32_t b1 = __float_as_uint(sv8[(k0 + cl + 4) * 8 + rw]);
            mma8(ca, a, b0, b1);
        }
        const int i1 = i0 + rw, i2 = i0 + rw + 8;
        const int ch0 = 2 * cl, ch1 = 2 * cl + 1;
        const int o0 = g * 16 + 2 * ch0, o1 = g * 16 + 2 * ch1;
        dst[o0 * 128 + i1] = ca[0];
        dst[o1 * 128 + i1] = ca[1];
        dst[o0 * 128 + i2] = ca[2];
        dst[o1 * 128 + i2] = ca[3];
        float s0 = ca[0] + ca[2], s02 = ca[0] * ca[0] + ca[2] * ca[2];
        float s1 = ca[1] + ca[3], s12 = ca[1] * ca[1] + ca[3] * ca[3];
        s0 = rwSum(s0); s02 = rwSum(s02); s1 = rwSum(s1); s12 = rwSum(s12);
        if (rw == 0) {
            atomicAdd(&g_outStats[o0 * 2], s0);
            atomicAdd(&g_outStats[o0 * 2 + 1], s02);
            atomicAdd(&g_outStats[o1 * 2], s1);
            atomicAdd(&g_outStats[o1 * 2 + 1], s12);
        }
    } else {
        // ame reduce: warp handles one channel; lane covers 4 consecutive i
        const int ch = w - 8;
        const int iB = lane * 4;
        float4 v0 = *(const float4*)(amePart + ch * 512 + 0 * 128 + iB);
        float4 v1 = *(const float4*)(amePart + ch * 512 + 1 * 128 + iB);
        float4 v2 = *(const float4*)(amePart + ch * 512 + 2 * 128 + iB);
        float4 v3 = *(const float4*)(amePart + ch * 512 + 3 * 128 + iB);
        float4 r4 = make_float4(v0.x + v1.x + v2.x + v3.x,
                                v0.y + v1.y + v2.y + v3.y,
                                v0.z + v1.z + v2.z + v3.z,
                                v0.w + v1.w + v2.w + v3.w);
        const int o = g * 16 + 2 * ch + 1;
        *(float4*)(dst + o * 128 + iB) = r4;
        float sE = r4.x + r4.y + r4.z + r4.w;
        float sE2 = r4.x * r4.x + r4.y * r4.y + r4.z * r4.z + r4.w * r4.w;
        sE = warpSum(sE); sE2 = warpSum(sE2);
        if (lane == 0) {
            atomicAdd(&g_outStats[o * 2], sE);
            atomicAdd(&g_outStats[o * 2 + 1], sE2);
        }
    }
}

// ---------------- G: fused out-BN finalize + y = bn[2oc] + bn[2oc+1] ----------------
// each block spans exactly one oc (256 idx < 8192 span) -> compute 2 ch params in-block
__global__ __launch_bounds__(256) void kG(const float* __restrict__ gamma_out,
                                          const float* __restrict__ beta_out,
                                          float* __restrict__ y) {
    __shared__ float sc[2], sf[2];
    int base = blockIdx.x * 256;
    if (threadIdx.x < 2) {
        int oc = (base >> 13) & 127;
        int o = oc * 2 + threadIdx.x;
        const float N = 16384.f;
        float S = g_outStats[o * 2], S2 = g_outStats[o * 2 + 1];
        float mean = S / N;
        float var = S2 / N - mean * mean;
        float s = gamma_out[o] * rsqrtf(var + EPSF);
        sc[threadIdx.x] = s;
        sf[threadIdx.x] = beta_out[o] - mean * s;
    }
    __syncthreads();
    int idx = base + threadIdx.x;
    int wpos = idx & 127;
    int h = (idx >> 7) & 63;
    int oc = (idx >> 13) & 127;
    int b0 = idx >> 20;
    int bh = b0 * 64 + h;
    int o = oc * 2;
    float v0 = g_outraw[(size_t)bh * 32768 + o * 128 + wpos];
    float v1 = g_outraw[(size_t)bh * 32768 + (o + 1) * 128 + wpos];
    y[idx] = (v0 * sc[0] + sf[0]) + (v1 * sc[1] + sf[1]);
}

// ---------------- launch ----------------
extern "C" void kernel_launch(void* const* d_in, const int* in_sizes, int n_in,
                              void* d_out, int out_size) {
    const float* x  = (const float*)d_in[0];
    const float* W  = (const float*)d_in[1];
    const float* gq = (const float*)d_in[2];
    const float* bq = (const float*)d_in[3];
    const float* re = (const float*)d_in[4];
    const float* gs = (const float*)d_in[5];
    // beta_sim (d_in[6]) cancels inside softmax — unused
    const float* go = (const float*)d_in[7];
    const float* bo = (const float*)d_in[8];
    float* y = (float*)d_out;

    const int SMEM_A = (16896 + 128 * 68) * 4;       // 102400
    const int SMEM_C = 20480 * 4;                    // 81920 -> 2 CTAs/SM
    const int SMEM_E = 28288 * 4;                    // 113152 -> 2 CTAs/SM

    cudaFuncSetAttribute(kA, cudaFuncAttributeMaxDynamicSharedMemorySize, SMEM_A);
    cudaFuncSetAttribute(kC, cudaFuncAttributeMaxDynamicSharedMemorySize, SMEM_C);
    cudaFuncSetAttribute(kE, cudaFuncAttributeMaxDynamicSharedMemorySize, SMEM_E);

    kZero<<<1, 512>>>();
    kA<<<dim3(4, 128), 128, SMEM_A>>>(x, W);
    kC<<<dim3(16, 128), 512, SMEM_C>>>(re, gq, bq);
    kE<<<dim3(16, 128), 512, SMEM_E>>>(re, gq, bq, gs);
    kG<<<8192, 256>>>(go, bo, y);
}